// round 1
// baseline (speedup 1.0000x reference)
#include <cuda_runtime.h>
#include <cuda_bf16.h>

// DynamicMaskHead fused kernel:
//   per-instance 3-layer 1x1-conv MLP heads (body/edge/fused) +
//   aligned_bilinear x2 upsample + sigmoid, all in one kernel.
//
// Shapes (fixed by the problem instance):
//   mask_feats_*   : [2, 8, 100, 152] f32
//   mask_head_params: [128, 419] f32
//   output         : 3 x [128, 1, 200, 304] f32, concatenated (b, e, f)

#define Hh   100
#define Wd   152
#define HWd  15200
#define OH   200
#define OW   304
#define OT   16      // output rows per block tile
#define LR   10      // max logits rows per tile (8 + halo)
#define NPAR 419

// One MLP head: 10 -> 8 (relu) -> 8 (relu, kept as x2) -> 1
__device__ __forceinline__ void run_head(
    const float* __restrict__ w1, const float* __restrict__ b1,
    const float* __restrict__ w2, const float* __restrict__ b2,
    const float* __restrict__ w3, float b3,
    const float4 f[8], const float relx[4], float rely,
    float x2[8][4], float l[4])
{
    float x1[8][4];
#pragma unroll
    for (int c = 0; c < 8; c++) {
        const float* wr = w1 + c * 10;
        float a[4];
#pragma unroll
        for (int p = 0; p < 4; p++)
            a[p] = fmaf(wr[0], relx[p], fmaf(wr[1], rely, b1[c]));
#pragma unroll
        for (int k = 0; k < 8; k++) {
            const float w = wr[2 + k];
            a[0] = fmaf(w, f[k].x, a[0]);
            a[1] = fmaf(w, f[k].y, a[1]);
            a[2] = fmaf(w, f[k].z, a[2]);
            a[3] = fmaf(w, f[k].w, a[3]);
        }
#pragma unroll
        for (int p = 0; p < 4; p++) x1[c][p] = fmaxf(a[p], 0.0f);
    }
#pragma unroll
    for (int c = 0; c < 8; c++) {
        const float* wr = w2 + c * 8;
        float a[4];
#pragma unroll
        for (int p = 0; p < 4; p++) a[p] = b2[c];
#pragma unroll
        for (int k = 0; k < 8; k++) {
            const float w = wr[k];
#pragma unroll
            for (int p = 0; p < 4; p++) a[p] = fmaf(w, x1[k][p], a[p]);
        }
#pragma unroll
        for (int p = 0; p < 4; p++) x2[c][p] = fmaxf(a[p], 0.0f);
    }
#pragma unroll
    for (int p = 0; p < 4; p++) l[p] = b3;
#pragma unroll
    for (int k = 0; k < 8; k++) {
        const float w = w3[k];
#pragma unroll
        for (int p = 0; p < 4; p++) l[p] = fmaf(w, x2[k][p], l[p]);
    }
}

__global__ void __launch_bounds__(256)
dmh_kernel(const float* __restrict__ feats_b,
           const float* __restrict__ feats_e,
           const float* __restrict__ params,
           const float* __restrict__ locs,
           const float* __restrict__ soi_arr,
           const int*   __restrict__ im_inds,
           const int*   __restrict__ fpn,
           const int*   __restrict__ stride_ptr,
           float*       __restrict__ out,
           int n_inst)
{
    const int tid  = threadIdx.x;
    const int tile = blockIdx.x;
    const int inst = blockIdx.y;
    const int i0   = tile * OT;

    __shared__ float sp[NPAR];
    __shared__ float sl[3][LR][Wd];

    // cooperative param load for this instance
    const float* prow = params + inst * NPAR;
    for (int t = tid; t < NPAR; t += 256) sp[t] = prow[t];

    const int   stride  = stride_ptr ? *stride_ptr : 8;
    const float fstride = (float)stride;
    const float halfs   = (float)(stride >> 1);

    const float ix  = locs[inst * 2 + 0];
    const float iy  = locs[inst * 2 + 1];
    const float inv = 1.0f / soi_arr[fpn[inst]];
    const int   im  = im_inds[inst];

    // logits rows needed for output rows [i0, i0+OT)
    const int ybase = max(0, 8 * tile - 1);
    const int yend  = min(Hh - 1, 8 * tile + 8);
    const int nrows = yend - ybase + 1;

    __syncthreads();

    const float* w1b = sp;       const float* w2b = sp + 80;  const float* w3b = sp + 144;
    const float* b1b = sp + 152; const float* b2b = sp + 160; const float  b3b = sp[168];
    const float* w1e = sp + 169; const float* w2e = sp + 249; const float* w3e = sp + 313;
    const float* b1e = sp + 321; const float* b2e = sp + 329; const float  b3e = sp[337];
    const float* wf1 = sp + 338; const float* wf2 = sp + 402; const float* bf1 = sp + 410;
    const float  bf2 = sp[418];

    const float* fbB = feats_b + (long long)im * 8 * HWd;
    const float* fbE = feats_e + (long long)im * 8 * HWd;

    // ---------------- Phase B: compute logits strip into smem ----------------
    const int ngroups = nrows * (Wd / 4);   // 38 column-groups per row
    for (int g = tid; g < ngroups; g += 256) {
        const int srow = g / 38;
        const int c0   = (g - srow * 38) * 4;
        const int y    = ybase + srow;

        const float rely = (iy - ((float)y * fstride + halfs)) * inv;
        float relx[4];
#pragma unroll
        for (int p = 0; p < 4; p++)
            relx[p] = (ix - ((float)(c0 + p) * fstride + halfs)) * inv;

        const int base = y * Wd + c0;

        float4 f[8];
#pragma unroll
        for (int k = 0; k < 8; k++)
            f[k] = *(const float4*)(fbB + k * HWd + base);

        float x2b[8][4], lb[4];
        run_head(w1b, b1b, w2b, b2b, w3b, b3b, f, relx, rely, x2b, lb);

#pragma unroll
        for (int k = 0; k < 8; k++)
            f[k] = *(const float4*)(fbE + k * HWd + base);

        float x2e[8][4], le[4];
        run_head(w1e, b1e, w2e, b2e, w3e, b3e, f, relx, rely, x2e, le);

        // fused head: input = x2b + x2e, layers 8->8 (relu) -> 1
        float xf[8][4];
#pragma unroll
        for (int k = 0; k < 8; k++)
#pragma unroll
            for (int p = 0; p < 4; p++) xf[k][p] = x2b[k][p] + x2e[k][p];

        float lf[4];
#pragma unroll
        for (int p = 0; p < 4; p++) lf[p] = bf2;
#pragma unroll
        for (int c = 0; c < 8; c++) {
            const float* wr = wf1 + c * 8;
            float a[4];
#pragma unroll
            for (int p = 0; p < 4; p++) a[p] = bf1[c];
#pragma unroll
            for (int k = 0; k < 8; k++) {
                const float w = wr[k];
#pragma unroll
                for (int p = 0; p < 4; p++) a[p] = fmaf(w, xf[k][p], a[p]);
            }
            const float wo = wf2[c];
#pragma unroll
            for (int p = 0; p < 4; p++) lf[p] = fmaf(wo, fmaxf(a[p], 0.0f), lf[p]);
        }

#pragma unroll
        for (int p = 0; p < 4; p++) {
            sl[0][srow][c0 + p] = lb[p];
            sl[1][srow][c0 + p] = le[p];
            sl[2][srow][c0 + p] = lf[p];
        }
    }
    __syncthreads();

    // ---------------- Phase C: aligned_bilinear x2 + sigmoid -----------------
    const int rows_here = min(OT, OH - i0);
    const int npix      = rows_here * OW;
    const long long ostride = (long long)n_inst * OH * OW;
    float* ob = out + (long long)inst * (OH * OW);

    for (int idx = tid; idx < npix; idx += 256) {
        const int di = idx / OW;
        const int j  = idx - di * OW;
        const int i  = i0 + di;
        const int r  = (i > 0) ? i - 1 : 0;
        const int c  = (j > 0) ? j - 1 : 0;
        const int y0 = r >> 1;
        const int x0 = c >> 1;
        const float fy = (r & 1) ? 0.5f : 0.0f;
        const float fx = (c & 1) ? 0.5f : 0.0f;
        const int y1  = min(y0 + 1, Hh - 1);
        const int x1c = min(x0 + 1, Wd - 1);
        const int s0 = y0 - ybase;
        const int s1 = y1 - ybase;
        const int oidx = i * OW + j;

#pragma unroll
        for (int m = 0; m < 3; m++) {
            const float v00 = sl[m][s0][x0],  v01 = sl[m][s0][x1c];
            const float v10 = sl[m][s1][x0],  v11 = sl[m][s1][x1c];
            const float vt = v00 + fx * (v01 - v00);
            const float vb = v10 + fx * (v11 - v10);
            const float v  = vt + fy * (vb - vt);
            ob[m * ostride + oidx] = __fdividef(1.0f, 1.0f + __expf(-v));
        }
    }
}

extern "C" void kernel_launch(void* const* d_in, const int* in_sizes, int n_in,
                              void* d_out, int out_size)
{
    const float* feats_b = (const float*)d_in[0];
    const float* feats_e = (const float*)d_in[1];
    const float* params  = (const float*)d_in[2];
    const float* locs    = (const float*)d_in[3];
    const float* soi     = (const float*)d_in[4];
    const int*   im      = (const int*)d_in[5];
    const int*   fpn     = (const int*)d_in[6];
    const int*   stridep = (n_in > 7) ? (const int*)d_in[7] : nullptr;

    const int n_inst = in_sizes[5];                 // 128 (im_inds count)
    dim3 grid((OH + OT - 1) / OT, n_inst);          // 13 x 128
    dmh_kernel<<<grid, 256>>>(feats_b, feats_e, params, locs, soi,
                              im, fpn, stridep, (float*)d_out, n_inst);
}